// round 17
// baseline (speedup 1.0000x reference)
#include <cuda_runtime.h>
#include <cuda_fp16.h>
#include <cstdint>

// ---------------------------------------------------------------------------
// GCN (3-layer) on GB300 — CSR gather (LDG.128, 16 edges/iter), fp16 interm.
//   GEMM1: xw1 = x @ W1 (fp16, stride 32 half2); then prescale xw1 *= dinv.
//   GEMM2/3 prescale by dinv[row] directly.
//   gatherNv: warp per node; lane (g=lane>>3, c=lane&7); 4 row LDG.128 in
//   flight per lane per iteration; shfl_xor reduce across edge slots.
//   CSR build (4-edge/thread atomics) on a side stream concurrent with GEMM1.
// ---------------------------------------------------------------------------

#define N_MAX 100000
#define E_MAX 1600000

static __device__ __align__(256) __half2 g_bufA[(size_t)N_MAX * 32];  // stride 32
static __device__ __align__(256) __half2 g_bufB[(size_t)N_MAX * 32];
static __device__ __align__(256) float g_dinv[N_MAX];
static __device__ int g_degi[N_MAX];
static __device__ int g_cursor[N_MAX];
static __device__ int g_ptr[N_MAX + 1];
static __device__ int g_bsum[1024];
static __device__ int g_erow[E_MAX];
static __device__ int g_mode;  // 0 = int64 indices, 1 = int32 indices

// ---------------- dtype detection ----------------
__global__ void detect_mode_kernel(const void* ei, int cnt64, int n) {
    __shared__ int bad;
    if (threadIdx.x == 0) bad = 0;
    __syncthreads();
    const long long* p = (const long long*)ei;
    int cnt = min(cnt64, 1024);
    for (int i = threadIdx.x; i < cnt; i += blockDim.x) {
        unsigned long long v = (unsigned long long)p[i];
        if (v >= (unsigned long long)n) atomicOr(&bad, 1);
    }
    __syncthreads();
    if (threadIdx.x == 0) g_mode = bad ? 1 : 0;
}

// ---------------- CSR build (4 edges per thread for atomic MLP) -------------

__device__ __forceinline__ void load4_idx(const void* ei, long long base,
                                          int mode, int rem, int* v) {
    // load 4 indices at positions base..base+3 (rem = how many are valid)
    if (mode) {
        if (rem >= 4) {
            int4 u = __ldg((const int4*)((const int*)ei + base));
            v[0] = u.x; v[1] = u.y; v[2] = u.z; v[3] = u.w;
        } else {
            for (int k = 0; k < 4; k++)
                v[k] = (k < rem) ? ((const int*)ei)[base + k] : -1;
        }
    } else {
        if (rem >= 4) {
            longlong2 a = __ldg((const longlong2*)((const long long*)ei + base));
            longlong2 b = __ldg((const longlong2*)((const long long*)ei + base) + 1);
            v[0] = (int)a.x; v[1] = (int)a.y; v[2] = (int)b.x; v[3] = (int)b.y;
        } else {
            for (int k = 0; k < 4; k++)
                v[k] = (k < rem) ? (int)((const long long*)ei)[base + k] : -1;
        }
    }
}

__global__ void deg_count_kernel(int* degi, const void* ei, int E, int n) {
    int t = blockIdx.x * blockDim.x + threadIdx.x;
    long long e0 = (long long)t * 4;
    if (e0 >= E) return;
    int rem = (int)min((long long)4, (long long)E - e0);
    int mode = g_mode;
    int c[4];
    load4_idx(ei, (long long)E + e0, mode, rem, c);   // cols
#pragma unroll
    for (int k = 0; k < 4; k++) {
        unsigned cc = (unsigned)c[k];
        if (cc < (unsigned)n) atomicAdd(&degi[cc], 1);
    }
}

__global__ void scanA_kernel(const int* degi, int* ptr, int* bsum, int n) {
    __shared__ int s[256];
    int i = blockIdx.x * 256 + threadIdx.x;
    int v = (i < n) ? degi[i] : 0;
    s[threadIdx.x] = v;
    __syncthreads();
    for (int off = 1; off < 256; off <<= 1) {
        int t = (threadIdx.x >= off) ? s[threadIdx.x - off] : 0;
        __syncthreads();
        s[threadIdx.x] += t;
        __syncthreads();
    }
    if (i < n) ptr[i] = s[threadIdx.x] - v;   // exclusive within block
    if (threadIdx.x == 255) bsum[blockIdx.x] = s[255];
}

__global__ void scanB_kernel(int* bsum, int nb) {
    __shared__ int s[1024];
    int v = (threadIdx.x < nb) ? bsum[threadIdx.x] : 0;
    s[threadIdx.x] = v;
    __syncthreads();
    for (int off = 1; off < 1024; off <<= 1) {
        int t = (threadIdx.x >= off) ? s[threadIdx.x - off] : 0;
        __syncthreads();
        s[threadIdx.x] += t;
        __syncthreads();
    }
    if (threadIdx.x < nb) bsum[threadIdx.x] = s[threadIdx.x] - v;  // exclusive
}

__global__ void scanC_fused_kernel(int* ptr, const int* bsum, int* cursor,
                                   float* dinv, const int* degi, int n, int E) {
    int i = blockIdx.x * 256 + threadIdx.x;
    if (i < n) {
        int p = ptr[i] + bsum[blockIdx.x];
        ptr[i] = p;
        cursor[i] = p;
        dinv[i] = rsqrtf(1.0f + (float)degi[i]);     // +1 self loop
    }
    if (i == 0) ptr[n] = E;
}

__global__ void fill_kernel(const void* ei, int* cursor, int* erow, int E, int n) {
    int t = blockIdx.x * blockDim.x + threadIdx.x;
    long long e0 = (long long)t * 4;
    if (e0 >= E) return;
    int rem = (int)min((long long)4, (long long)E - e0);
    int mode = g_mode;
    int r[4], c[4];
    load4_idx(ei, e0, mode, rem, r);                  // rows
    load4_idx(ei, (long long)E + e0, mode, rem, c);   // cols
    int pos[4];
#pragma unroll
    for (int k = 0; k < 4; k++) {
        unsigned cc = (unsigned)c[k];
        pos[k] = (cc < (unsigned)n && (unsigned)r[k] < (unsigned)n)
                     ? atomicAdd(&cursor[cc], 1) : -1;
    }
#pragma unroll
    for (int k = 0; k < 4; k++)
        if (pos[k] >= 0) erow[pos[k]] = r[k];
}

// ---------------- packed f32x2 FMA ----------------

__device__ __forceinline__ void fma2(unsigned long long& d,
                                     unsigned long long a,
                                     unsigned long long b) {
    asm("fma.rn.f32x2 %0, %1, %2, %3;" : "=l"(d) : "l"(a), "l"(b), "l"(d));
}

__device__ __forceinline__ unsigned long long pack_dup(float v) {
    unsigned long long r;
    asm("mov.b64 %0, {%1, %2};" : "=l"(r) : "f"(v), "f"(v));
    return r;
}

// ---------------- GEMM (+ optional dinv scale) -> half2, stride 32 ----------

template <int DIN, int DOUT, bool HALF_IN, bool SCALE>
__global__ void gemm_kernel(const void* __restrict__ Xv,
                            const float* __restrict__ W,
                            const float* __restrict__ dinv,
                            __half2* __restrict__ xwh,
                            int M) {
    __shared__ __align__(16) float Ws[DIN * DOUT];
    const int tid = threadIdx.x;           // 0..127
    const int row = blockIdx.x * 128 + tid;

    for (int i = tid; i < DIN * DOUT; i += 128) Ws[i] = W[i];
    __syncthreads();

    unsigned long long a2[DOUT / 2];
#pragma unroll
    for (int j = 0; j < DOUT / 2; j++) a2[j] = 0ull;

    const bool act = (row < M);

#pragma unroll
    for (int k0 = 0; k0 < DIN; k0 += 16) {
        float xr[16];
        if (act) {
            if (HALF_IN) {
                const uint4* src = (const uint4*)((const __half*)Xv + (size_t)row * DIN + k0);
                uint4 u0 = __ldg(src);
                uint4 u1 = __ldg(src + 1);
                const unsigned* uu = &u0.x;
#pragma unroll
                for (int q = 0; q < 4; q++) {
                    float2 f = __half22float2(*(const __half2*)&uu[q]);
                    xr[q * 2] = f.x; xr[q * 2 + 1] = f.y;
                }
                const unsigned* vv = &u1.x;
#pragma unroll
                for (int q = 0; q < 4; q++) {
                    float2 f = __half22float2(*(const __half2*)&vv[q]);
                    xr[8 + q * 2] = f.x; xr[8 + q * 2 + 1] = f.y;
                }
            } else {
                const float4* src = (const float4*)((const float*)Xv + (size_t)row * DIN + k0);
#pragma unroll
                for (int q = 0; q < 4; q++) {
                    float4 v = __ldg(src + q);
                    xr[q * 4] = v.x; xr[q * 4 + 1] = v.y;
                    xr[q * 4 + 2] = v.z; xr[q * 4 + 3] = v.w;
                }
            }
        } else {
#pragma unroll
            for (int q = 0; q < 16; q++) xr[q] = 0.f;
        }
#pragma unroll
        for (int k = 0; k < 16; k++) {
            unsigned long long xv2 = pack_dup(xr[k]);
            const float* wrow = &Ws[(k0 + k) * DOUT];
#pragma unroll
            for (int j = 0; j < DOUT; j += 4) {
                ulonglong2 ww = *(const ulonglong2*)&wrow[j];
                fma2(a2[j / 2],     xv2, ww.x);
                fma2(a2[j / 2 + 1], xv2, ww.y);
            }
        }
    }

    if (act) {
        float s = SCALE ? dinv[row] : 1.0f;
        __half2* dst = xwh + (size_t)row * 32;      // padded stride
#pragma unroll
        for (int p = 0; p < DOUT / 2; p += 2) {
            float x0, x1, x2, x3;
            asm("mov.b64 {%0, %1}, %2;" : "=f"(x0), "=f"(x1) : "l"(a2[p]));
            asm("mov.b64 {%0, %1}, %2;" : "=f"(x2), "=f"(x3) : "l"(a2[p + 1]));
            uint2 pack;
            __half2 h0 = __floats2half2_rn(x0 * s, x1 * s);
            __half2 h1 = __floats2half2_rn(x2 * s, x3 * s);
            pack.x = *(unsigned*)&h0;
            pack.y = *(unsigned*)&h1;
            *(uint2*)&dst[p] = pack;
        }
    }
}

// ---------------- prescale: xw *= dinv[row] (row stride 32 half2) -----------

__global__ void prescale_kernel(__half2* __restrict__ xw,
                                const float* __restrict__ dinv, int n) {
    int i = blockIdx.x * blockDim.x + threadIdx.x;   // one uint4 = 4 half2
    if (i >= n * 8) return;
    int row = i >> 3;
    float s = __ldg(&dinv[row]);
    uint4 v = *((uint4*)xw + i);
    unsigned* u = &v.x;
#pragma unroll
    for (int q = 0; q < 4; q++) {
        float2 f = __half22float2(*(__half2*)&u[q]);
        __half2 h = __floats2half2_rn(f.x * s, f.y * s);
        u[q] = *(unsigned*)&h;
    }
    *((uint4*)xw + i) = v;
}

// ---------------- vectorized gather: D=64, 16 edges/iter --------------------

__device__ __forceinline__ void acc_u4(float2* acc, uint4 v) {
    const unsigned* u = &v.x;
#pragma unroll
    for (int q = 0; q < 4; q++) {
        float2 f = __half22float2(*(const __half2*)&u[q]);
        acc[q].x += f.x; acc[q].y += f.y;
    }
}

__global__ void gather64v_kernel(const __half2* __restrict__ xwh,
                                 const int* __restrict__ ptr,
                                 const int* __restrict__ erow,
                                 const float* __restrict__ dinv,
                                 const float* __restrict__ bias,
                                 __half2* __restrict__ out,
                                 int n) {
    const int lane = threadIdx.x & 31;
    const int g = lane >> 3;
    const int c = lane & 7;
    const int node = blockIdx.x * 8 + (threadIdx.x >> 5);
    if (node >= n) return;

    const int start = __ldg(&ptr[node]);
    const int end   = __ldg(&ptr[node + 1]);

    float2 acc[4];
#pragma unroll
    for (int q = 0; q < 4; q++) acc[q] = make_float2(0.f, 0.f);

    // 16 edges per iteration: 4 independent id loads, 4 independent row LDG.128
    for (int j = start; j < end; j += 16) {
        int id[4];
#pragma unroll
        for (int u = 0; u < 4; u++) {
            int jj = j + 4 * u + g;
            id[u] = (jj < end) ? __ldg(&erow[jj]) : -1;
        }
        uint4 v[4];
#pragma unroll
        for (int u = 0; u < 4; u++)
            v[u] = (id[u] >= 0) ? __ldg((const uint4*)(xwh + (size_t)id[u] * 32) + c)
                                : make_uint4(0, 0, 0, 0);
#pragma unroll
        for (int u = 0; u < 4; u++) acc_u4(acc, v[u]);
    }

    // reduce across edge slots (lane bits 3,4)
#pragma unroll
    for (int off = 8; off <= 16; off <<= 1) {
#pragma unroll
        for (int q = 0; q < 4; q++) {
            acc[q].x += __shfl_xor_sync(0xffffffffu, acc[q].x, off);
            acc[q].y += __shfl_xor_sync(0xffffffffu, acc[q].y, off);
        }
    }

    if (g == 0) {
        uint4 sv = __ldg((const uint4*)(xwh + (size_t)node * 32) + c);
        const unsigned* su = &sv.x;
        float s = __ldg(&dinv[node]);
        float4 b0 = __ldg((const float4*)(bias + c * 8));
        float4 b1 = __ldg((const float4*)(bias + c * 8 + 4));
        float bf[8] = {b0.x, b0.y, b0.z, b0.w, b1.x, b1.y, b1.z, b1.w};
        uint4 ov;
        unsigned* ou = &ov.x;
#pragma unroll
        for (int q = 0; q < 4; q++) {
            float2 sf = __half22float2(*(const __half2*)&su[q]);
            float ox = fmaxf((acc[q].x + sf.x) * s + bf[2 * q], 0.f);
            float oy = fmaxf((acc[q].y + sf.y) * s + bf[2 * q + 1], 0.f);
            __half2 h = __floats2half2_rn(ox, oy);
            ou[q] = *(unsigned*)&h;
        }
        *((uint4*)(out + (size_t)node * 32) + c) = ov;
    }
}

// ---------------- vectorized gather: final D=40, fp32 out -------------------

__global__ void gather40v_kernel(const __half2* __restrict__ xwh,
                                 const int* __restrict__ ptr,
                                 const int* __restrict__ erow,
                                 const float* __restrict__ dinv,
                                 const float* __restrict__ bias,
                                 float* __restrict__ out,
                                 int n) {
    const int lane = threadIdx.x & 31;
    const int g = lane >> 3;
    const int c = lane & 7;
    const int node = blockIdx.x * 8 + (threadIdx.x >> 5);
    if (node >= n) return;

    const int start = __ldg(&ptr[node]);
    const int end   = __ldg(&ptr[node + 1]);
    const bool live = (c < 5);

    float2 acc[4];
#pragma unroll
    for (int q = 0; q < 4; q++) acc[q] = make_float2(0.f, 0.f);

    for (int j = start; j < end; j += 16) {
        int id[4];
#pragma unroll
        for (int u = 0; u < 4; u++) {
            int jj = j + 4 * u + g;
            id[u] = (live && jj < end) ? __ldg(&erow[jj]) : -1;
        }
        uint4 v[4];
#pragma unroll
        for (int u = 0; u < 4; u++)
            v[u] = (id[u] >= 0) ? __ldg((const uint4*)(xwh + (size_t)id[u] * 32) + c)
                                : make_uint4(0, 0, 0, 0);
#pragma unroll
        for (int u = 0; u < 4; u++) acc_u4(acc, v[u]);
    }

#pragma unroll
    for (int off = 8; off <= 16; off <<= 1) {
#pragma unroll
        for (int q = 0; q < 4; q++) {
            acc[q].x += __shfl_xor_sync(0xffffffffu, acc[q].x, off);
            acc[q].y += __shfl_xor_sync(0xffffffffu, acc[q].y, off);
        }
    }

    if (g == 0 && live) {
        uint4 sv = __ldg((const uint4*)(xwh + (size_t)node * 32) + c);
        const unsigned* su = &sv.x;
        float s = __ldg(&dinv[node]);
        float4 b0 = __ldg((const float4*)(bias + c * 8));
        float4 b1 = __ldg((const float4*)(bias + c * 8 + 4));
        float bf[8] = {b0.x, b0.y, b0.z, b0.w, b1.x, b1.y, b1.z, b1.w};
        float o[8];
#pragma unroll
        for (int q = 0; q < 4; q++) {
            float2 sf = __half22float2(*(const __half2*)&su[q]);
            o[2 * q]     = (acc[q].x + sf.x) * s + bf[2 * q];
            o[2 * q + 1] = (acc[q].y + sf.y) * s + bf[2 * q + 1];
        }
        float* dst = out + (size_t)node * 40 + c * 8;
        *(float4*)dst       = make_float4(o[0], o[1], o[2], o[3]);
        *(float4*)(dst + 4) = make_float4(o[4], o[5], o[6], o[7]);
    }
}

// ---------------- launch ----------------

extern "C" void kernel_launch(void* const* d_in, const int* in_sizes, int n_in,
                              void* d_out, int out_size) {
    int i_x = -1, i_ei = -1, i_w1 = -1, i_w2 = -1, i_w3 = -1;
    int i_b1 = -1, i_b2 = -1, i_b3 = -1;
    for (int i = 0; i < n_in; i++) {
        int s = in_sizes[i];
        if      (s == 12800000) i_x  = i;
        else if (s == 3200000)  i_ei = i;
        else if (s == 8192)     i_w1 = i;
        else if (s == 4096)     i_w2 = i;
        else if (s == 2560)     i_w3 = i;
        else if (s == 40)       i_b3 = i;
        else if (s == 64)       { if (i_b1 < 0) i_b1 = i; else i_b2 = i; }
    }
    if (i_x < 0 || i_ei < 0 || i_w1 < 0 || i_b1 < 0 || i_w2 < 0 ||
        i_b2 < 0 || i_w3 < 0 || i_b3 < 0) {
        i_x = 0; i_ei = 1; i_w1 = 2; i_b1 = 3; i_w2 = 4; i_b2 = 5; i_w3 = 6; i_b3 = 7;
    }

    const float* x  = (const float*)d_in[i_x];
    const void*  ei = d_in[i_ei];
    const float* W1 = (const float*)d_in[i_w1];
    const float* b1 = (const float*)d_in[i_b1];
    const float* W2 = (const float*)d_in[i_w2];
    const float* b2 = (const float*)d_in[i_b2];
    const float* W3 = (const float*)d_in[i_w3];
    const float* b3 = (const float*)d_in[i_b3];

    const int M = in_sizes[i_x] / 128;     // 100000
    const int E = in_sizes[i_ei] / 2;      // 1600000
    float* out = (float*)d_out;

    __half2 *pA, *pB;
    float* pDinv;
    int *pDeg, *pCur, *pPtr, *pBsum, *pErow;
    cudaGetSymbolAddress((void**)&pA, g_bufA);
    cudaGetSymbolAddress((void**)&pB, g_bufB);
    cudaGetSymbolAddress((void**)&pDinv, g_dinv);
    cudaGetSymbolAddress((void**)&pDeg, g_degi);
    cudaGetSymbolAddress((void**)&pCur, g_cursor);
    cudaGetSymbolAddress((void**)&pPtr, g_ptr);
    cudaGetSymbolAddress((void**)&pBsum, g_bsum);
    cudaGetSymbolAddress((void**)&pErow, g_erow);

    const int T = 256;
    const int nbN  = (M + 255) / 256;
    const int nbE4 = ((E + 3) / 4 + T - 1) / T;
    const int gM   = (M + 127) / 128;
    const int gV   = (M + 7) / 8;
    const int gP   = (M * 8 + T - 1) / T;

    cudaStream_t s2;
    cudaEvent_t evD, evF;
    bool forked = (cudaStreamCreateWithFlags(&s2, cudaStreamNonBlocking) == cudaSuccess) &&
                  (cudaEventCreateWithFlags(&evD, cudaEventDisableTiming) == cudaSuccess) &&
                  (cudaEventCreateWithFlags(&evF, cudaEventDisableTiming) == cudaSuccess);

    if (forked) {
        // side stream: complete CSR build; main stream: GEMM1 (unscaled)
        cudaEventRecord(evD, 0);
        cudaStreamWaitEvent(s2, evD, 0);
        detect_mode_kernel<<<1, 256, 0, s2>>>(ei, 2 * E, M);
        cudaMemsetAsync(pDeg, 0, (size_t)M * sizeof(int), s2);
        deg_count_kernel<<<nbE4, T, 0, s2>>>(pDeg, ei, E, M);
        scanA_kernel<<<nbN, 256, 0, s2>>>(pDeg, pPtr, pBsum, M);
        scanB_kernel<<<1, 1024, 0, s2>>>(pBsum, nbN);
        scanC_fused_kernel<<<nbN, 256, 0, s2>>>(pPtr, pBsum, pCur, pDinv, pDeg, M, E);
        fill_kernel<<<nbE4, T, 0, s2>>>(ei, pCur, pErow, E, M);
        cudaEventRecord(evF, s2);

        gemm_kernel<128, 64, false, false><<<gM, 128>>>(x, W1, pDinv, pA, M);
        cudaStreamWaitEvent(0, evF, 0);
    } else {
        detect_mode_kernel<<<1, 256>>>(ei, 2 * E, M);
        cudaMemsetAsync(pDeg, 0, (size_t)M * sizeof(int), 0);
        deg_count_kernel<<<nbE4, T>>>(pDeg, ei, E, M);
        scanA_kernel<<<nbN, 256>>>(pDeg, pPtr, pBsum, M);
        scanB_kernel<<<1, 1024>>>(pBsum, nbN);
        scanC_fused_kernel<<<nbN, 256>>>(pPtr, pBsum, pCur, pDinv, pDeg, M, E);
        fill_kernel<<<nbE4, T>>>(ei, pCur, pErow, E, M);
        gemm_kernel<128, 64, false, false><<<gM, 128>>>(x, W1, pDinv, pA, M);
    }

    // prescale xw1 by dinv (needs both GEMM1 and dinv ready)
    prescale_kernel<<<gP, T>>>(pA, pDinv, M);

    // Layer 1 aggregation (A -> B)
    gather64v_kernel<<<gV, 256>>>(pA, pPtr, pErow, pDinv, b1, pB, M);

    // Layer 2 (B -> A prescaled), aggregation (A -> B)
    gemm_kernel<64, 64, true, true><<<gM, 128>>>(pB, W2, pDinv, pA, M);
    gather64v_kernel<<<gV, 256>>>(pA, pPtr, pErow, pDinv, b2, pB, M);

    // Layer 3 (B -> A prescaled, 40 outs), final aggregation (A -> out)
    gemm_kernel<64, 40, true, true><<<gM, 128>>>(pB, W3, pDinv, pA, M);
    gather40v_kernel<<<gV, 256>>>(pA, pPtr, pErow, pDinv, b3, out, M);
}